// round 1
// baseline (speedup 1.0000x reference)
#include <cuda_runtime.h>
#include <math.h>

// ---------------------------------------------------------------------------
// Problem constants (shapes fixed by the dataset)
//   Ns = Nr = 100000, E = 600000, D = 128, A = 8, S = 64, H = 128
// ---------------------------------------------------------------------------
#define D_OUT 128
#define TN    32     // rows per block tile
#define KT    64     // K tile

#define MAX_E 600000
#define MAX_N 100000

// Scratch (allocation-free rule: __device__ globals)
__device__ float g_h  [(size_t)MAX_E * 128];   // hidden of edge MLP
__device__ float g_wt [(size_t)MAX_E * 128];   // per-edge TP weights
__device__ float g_sf [(size_t)MAX_N * 128];   // sender features (fctp lin1)
__device__ float g_sc [(size_t)MAX_N * 128];   // receiver self connection (fctp sc)
__device__ float g_rf [(size_t)MAX_N * 128];   // scattered receiver features
__device__ float g_ang[(size_t)MAX_N];         // receiver angle

// ---------------------------------------------------------------------------
// Plain GEMM: C[r, 0..127] = epi(scale * sum_k A[r][k] * W[k][w])
// Block: 128 threads, 32 rows x 128 cols, thread tile 4x8.
// ---------------------------------------------------------------------------
template<bool SILU>
__global__ __launch_bounds__(128)
void gemm128_kernel(const float* __restrict__ A, const float* __restrict__ W,
                    float* __restrict__ C, int R, int K, float scale)
{
    __shared__ __align__(16) float As[KT][TN + 4];
    __shared__ __align__(16) float Ws[KT][D_OUT];

    const int r0  = blockIdx.x * TN;
    const int tid = threadIdx.x;
    const int tx  = tid & 15;
    const int ty  = tid >> 4;
    const int w0  = tx * 8;
    const int n0  = ty * 4;

    float acc[4][8];
#pragma unroll
    for (int i = 0; i < 4; ++i)
#pragma unroll
        for (int j = 0; j < 8; ++j) acc[i][j] = 0.f;

    for (int k0 = 0; k0 < K; k0 += KT) {
        // A tile: 32 rows x 64 k (coalesced on k)
#pragma unroll
        for (int t = 0; t < (TN * KT) / 128; ++t) {
            int idx = tid + t * 128;
            int n = idx >> 6;       // idx / KT
            int k = idx & 63;       // idx % KT
            int r = r0 + n;
            As[k][n] = (r < R) ? A[(size_t)r * K + k0 + k] : 0.f;
        }
        // W tile: contiguous 32KB
        const float4* Wg = (const float4*)(W + (size_t)k0 * D_OUT);
#pragma unroll
        for (int t = 0; t < (KT * D_OUT / 4) / 128; ++t)
            ((float4*)Ws)[tid + t * 128] = Wg[tid + t * 128];
        __syncthreads();

#pragma unroll 4
        for (int k = 0; k < KT; ++k) {
            float a[4];
#pragma unroll
            for (int i = 0; i < 4; ++i) a[i] = As[k][n0 + i];
            float4 b0 = *(const float4*)&Ws[k][w0];
            float4 b1 = *(const float4*)&Ws[k][w0 + 4];
#pragma unroll
            for (int i = 0; i < 4; ++i) {
                acc[i][0] += a[i] * b0.x;  acc[i][1] += a[i] * b0.y;
                acc[i][2] += a[i] * b0.z;  acc[i][3] += a[i] * b0.w;
                acc[i][4] += a[i] * b1.x;  acc[i][5] += a[i] * b1.y;
                acc[i][6] += a[i] * b1.z;  acc[i][7] += a[i] * b1.w;
            }
        }
        __syncthreads();
    }

#pragma unroll
    for (int i = 0; i < 4; ++i) {
        int r = r0 + n0 + i;
        if (r < R) {
            float v[8];
#pragma unroll
            for (int j = 0; j < 8; ++j) {
                float x = acc[i][j] * scale;
                if (SILU) x = 1.679177f * x / (1.f + expf(-x));   // normalize2mom * silu
                v[j] = x;
            }
            float4* o = (float4*)(C + (size_t)r * D_OUT + w0);
            o[0] = make_float4(v[0], v[1], v[2], v[3]);
            o[1] = make_float4(v[4], v[5], v[6], v[7]);
        }
    }
}

// ---------------------------------------------------------------------------
// fctp: out[n,w] = scale * sum_{u<128, v<8} X[n,u] Y[n,v] W[(u*8+v)*128 + w]
// Same tiling as gemm128; A operand (outer product) built on the fly from
// xs (smem, per k-tile) and yr (registers, loop-invariant).
// COMBINE epilogue: out = cos(ang)*SC + sin(ang)*acc*scale
// ---------------------------------------------------------------------------
template<bool COMBINE>
__global__ __launch_bounds__(128)
void fctp_kernel(const float* __restrict__ X, const float* __restrict__ Y,
                 const float* __restrict__ W, float* __restrict__ C,
                 const float* __restrict__ SC, const float* __restrict__ ANG,
                 int N, float scale)
{
    __shared__ __align__(16) float Ws[KT][D_OUT];
    __shared__ float xs[TN][8];
    __shared__ float ys[TN][8];

    const int r0  = blockIdx.x * TN;
    const int tid = threadIdx.x;
    const int tx  = tid & 15;
    const int ty  = tid >> 4;
    const int w0  = tx * 8;
    const int n0  = ty * 4;

    // load attr tile once
#pragma unroll
    for (int t = 0; t < 2; ++t) {
        int idx = tid + t * 128;
        int n = idx >> 3, v = idx & 7;
        int r = r0 + n;
        ys[n][v] = (r < N) ? Y[(size_t)r * 8 + v] : 0.f;
    }
    __syncthreads();

    float yr[4][8];
#pragma unroll
    for (int i = 0; i < 4; ++i)
#pragma unroll
        for (int v = 0; v < 8; ++v) yr[i][v] = ys[n0 + i][v];

    float acc[4][8];
#pragma unroll
    for (int i = 0; i < 4; ++i)
#pragma unroll
        for (int j = 0; j < 8; ++j) acc[i][j] = 0.f;

    for (int kt = 0; kt < 16; ++kt) {
        const int u0 = kt * 8;
        // x chunk: 32 nodes x 8 u
#pragma unroll
        for (int t = 0; t < 2; ++t) {
            int idx = tid + t * 128;
            int n = idx >> 3, u = idx & 7;
            int r = r0 + n;
            xs[n][u] = (r < N) ? X[(size_t)r * 128 + u0 + u] : 0.f;
        }
        // W tile (contiguous: global k = u*8+v, tile covers k = kt*64 .. +63)
        const float4* Wg = (const float4*)(W + (size_t)kt * KT * D_OUT);
#pragma unroll
        for (int t = 0; t < 16; ++t)
            ((float4*)Ws)[tid + t * 128] = Wg[tid + t * 128];
        __syncthreads();

#pragma unroll 2
        for (int uu = 0; uu < 8; ++uu) {
            float a0[4];
#pragma unroll
            for (int i = 0; i < 4; ++i) a0[i] = xs[n0 + i][uu];
#pragma unroll
            for (int v = 0; v < 8; ++v) {
                const int k = uu * 8 + v;
                float4 b0 = *(const float4*)&Ws[k][w0];
                float4 b1 = *(const float4*)&Ws[k][w0 + 4];
#pragma unroll
                for (int i = 0; i < 4; ++i) {
                    float a = a0[i] * yr[i][v];
                    acc[i][0] += a * b0.x;  acc[i][1] += a * b0.y;
                    acc[i][2] += a * b0.z;  acc[i][3] += a * b0.w;
                    acc[i][4] += a * b1.x;  acc[i][5] += a * b1.y;
                    acc[i][6] += a * b1.z;  acc[i][7] += a * b1.w;
                }
            }
        }
        __syncthreads();
    }

#pragma unroll
    for (int i = 0; i < 4; ++i) {
        int r = r0 + n0 + i;
        if (r < N) {
            if (COMBINE) {
                float ang = ANG[r];
                float ca = cosf(ang), sa = sinf(ang);
                const float4* scp = (const float4*)(SC + (size_t)r * 128 + w0);
                float4 s0 = scp[0], s1 = scp[1];
                float4 o0, o1;
                o0.x = ca * s0.x + sa * acc[i][0] * scale;
                o0.y = ca * s0.y + sa * acc[i][1] * scale;
                o0.z = ca * s0.z + sa * acc[i][2] * scale;
                o0.w = ca * s0.w + sa * acc[i][3] * scale;
                o1.x = ca * s1.x + sa * acc[i][4] * scale;
                o1.y = ca * s1.y + sa * acc[i][5] * scale;
                o1.z = ca * s1.z + sa * acc[i][6] * scale;
                o1.w = ca * s1.w + sa * acc[i][7] * scale;
                float4* o = (float4*)(C + (size_t)r * 128 + w0);
                o[0] = o0; o[1] = o1;
            } else {
                float4* o = (float4*)(C + (size_t)r * 128 + w0);
                o[0] = make_float4(acc[i][0] * scale, acc[i][1] * scale,
                                   acc[i][2] * scale, acc[i][3] * scale);
                o[1] = make_float4(acc[i][4] * scale, acc[i][5] * scale,
                                   acc[i][6] * scale, acc[i][7] * scale);
            }
        }
    }
}

// ---------------------------------------------------------------------------
// Edge scatter: rf[dst] += wt[e] * sf[src] * eattr[e] / sqrt(32); warp/edge
// ---------------------------------------------------------------------------
__global__ void scatter_kernel(const float* __restrict__ wt, const float* __restrict__ sf,
                               const int* __restrict__ src, const int* __restrict__ dst,
                               const float* __restrict__ eattr, float* __restrict__ rf, int E)
{
    int gw   = (blockIdx.x * blockDim.x + threadIdx.x) >> 5;
    int lane = threadIdx.x & 31;
    if (gw >= E) return;
    int s = src[gw], d = dst[gw];
    float ea = eattr[gw] * 0.17677669529663687f;   // 1/sqrt(NUM_NEIGHBORS)
    float4 w4 = ((const float4*)(wt + (size_t)gw * 128))[lane];
    float4 s4 = ((const float4*)(sf + (size_t)s  * 128))[lane];
    float* o = rf + (size_t)d * 128 + lane * 4;
    atomicAdd(o + 0, w4.x * s4.x * ea);
    atomicAdd(o + 1, w4.y * s4.y * ea);
    atomicAdd(o + 2, w4.z * s4.z * ea);
    atomicAdd(o + 3, w4.w * s4.w * ea);
}

// ---------------------------------------------------------------------------
// Angle: ang[n] = 0.1/32 * sum_{u,v} rf[n,u] rattr[n,v] W3[u*8+v]; warp/node
// ---------------------------------------------------------------------------
__global__ void angle_kernel(const float* __restrict__ RF, const float* __restrict__ RA,
                             const float* __restrict__ W3, float* __restrict__ ANG, int N)
{
    int gw   = (blockIdx.x * blockDim.x + threadIdx.x) >> 5;
    int lane = threadIdx.x & 31;
    if (gw >= N) return;
    float ya[8];
#pragma unroll
    for (int v = 0; v < 8; ++v) ya[v] = RA[(size_t)gw * 8 + v];
    float sacc = 0.f;
#pragma unroll
    for (int uu = 0; uu < 4; ++uu) {
        int u = lane + uu * 32;
        float xv = RF[(size_t)gw * 128 + u];
#pragma unroll
        for (int v = 0; v < 8; ++v) sacc += xv * ya[v] * W3[u * 8 + v];
    }
#pragma unroll
    for (int off = 16; off; off >>= 1) sacc += __shfl_xor_sync(0xffffffffu, sacc, off);
    if (lane == 0) ANG[gw] = 0.003125f * sacc;   // 0.1 / 32
}

// ---------------------------------------------------------------------------
extern "C" void kernel_launch(void* const* d_in, const int* in_sizes, int n_in,
                              void* d_out, int out_size)
{
    const float* sender_input   = (const float*)d_in[0];
    const float* sender_attr    = (const float*)d_in[1];
    const float* receiver_input = (const float*)d_in[2];
    const float* receiver_attr  = (const float*)d_in[3];
    const int*   edge_src       = (const int*)  d_in[4];
    const int*   edge_dst       = (const int*)  d_in[5];
    const float* edge_attr      = (const float*)d_in[6];
    const float* edge_scalars   = (const float*)d_in[7];
    const float* W_sc           = (const float*)d_in[8];
    const float* W_lin1         = (const float*)d_in[9];
    const float* W_fc1          = (const float*)d_in[10];
    const float* W_fc2          = (const float*)d_in[11];
    const float* W_lin2         = (const float*)d_in[12];
    const float* W_lin3         = (const float*)d_in[13];

    const int Ns = in_sizes[0] / 128;
    const int Nr = in_sizes[2] / 128;
    const int E  = in_sizes[4];

    float *h_p, *wt_p, *sf_p, *sc_p, *rf_p, *ang_p;
    cudaGetSymbolAddress((void**)&h_p,   g_h);
    cudaGetSymbolAddress((void**)&wt_p,  g_wt);
    cudaGetSymbolAddress((void**)&sf_p,  g_sf);
    cudaGetSymbolAddress((void**)&sc_p,  g_sc);
    cudaGetSymbolAddress((void**)&rf_p,  g_rf);
    cudaGetSymbolAddress((void**)&ang_p, g_ang);

    const float FCTP_SCALE = 0.03125f;              // 1/sqrt(128*8)
    dim3 blk(128);

    // Edge MLP: h = SILU_NORM*silu(es @ Wfc1 / 8);  wt = h @ Wfc2 / sqrt(128)
    gemm128_kernel<true ><<<(E + TN - 1) / TN, blk>>>(edge_scalars, W_fc1, h_p,  E, 64,  0.125f);
    gemm128_kernel<false><<<(E + TN - 1) / TN, blk>>>(h_p,          W_fc2, wt_p, E, 128, 0.08838834764831845f);

    // Node fctps
    fctp_kernel<false><<<(Ns + TN - 1) / TN, blk>>>(sender_input,   sender_attr,   W_lin1, sf_p,
                                                    nullptr, nullptr, Ns, FCTP_SCALE);
    fctp_kernel<false><<<(Nr + TN - 1) / TN, blk>>>(receiver_input, receiver_attr, W_sc,   sc_p,
                                                    nullptr, nullptr, Nr, FCTP_SCALE);

    // Scatter-add over edges
    cudaMemsetAsync(rf_p, 0, (size_t)Nr * 128 * sizeof(float));
    scatter_kernel<<<((long long)E * 32 + 255) / 256, 256>>>(wt_p, sf_p, edge_src, edge_dst,
                                                             edge_attr, rf_p, E);

    // Angle + final fctp with sin/cos gating epilogue
    angle_kernel<<<((long long)Nr * 32 + 255) / 256, 256>>>(rf_p, receiver_attr, W_lin3, ang_p, Nr);
    fctp_kernel<true ><<<(Nr + TN - 1) / TN, blk>>>(rf_p, receiver_attr, W_lin2, (float*)d_out,
                                                    sc_p, ang_p, Nr, FCTP_SCALE);
}

// round 3
// speedup vs baseline: 2.3822x; 2.3822x over previous
#include <cuda_runtime.h>
#include <cuda_bf16.h>
#include <math.h>
#include <stdint.h>

// ---------------------------------------------------------------------------
// Shapes: Ns=Nr=100000, E=600000, D=128, A=8, S=64, H=128
// ---------------------------------------------------------------------------
#define MAX_E 600000
#define MAX_N 100000

// Scratch (__device__ globals; allocation-free rule)
__device__ float g_wt [(size_t)MAX_E * 128];   // per-edge TP weights
__device__ float g_sf [(size_t)MAX_N * 128];   // sender features
__device__ float g_sc [(size_t)MAX_N * 128];   // receiver self connection
__device__ float g_rf [(size_t)MAX_N * 128];   // scattered receiver features
__device__ float g_ang[(size_t)MAX_N];         // receiver angle
// Prepped weights, bf16 n-major [128 n][K k]; slots of 256KB (max K=1024)
// ids: 0=fc1_h 1=fc1_l 2=fc2_h 3=fc2_l 4=lin1_h 5=lin1_l 6=sc_h 7=sc_l 8=lin2_h 9=lin2_l
__device__ __align__(1024) uint8_t g_wp[10][262144];

// ---------------------------------------------------------------------------
// mma.sync / ldmatrix helpers (sm_80+, no arch-a gating)
// ---------------------------------------------------------------------------
__device__ __forceinline__ uint32_t smem_u32(const void* p) {
    uint32_t a;
    asm("{ .reg .u64 t; cvta.to.shared.u64 t, %1; cvt.u32.u64 %0, t; }" : "=r"(a) : "l"(p));
    return a;
}

__device__ __forceinline__ void mma16816(float* d, const uint32_t* a, const uint32_t* b) {
    asm volatile(
        "mma.sync.aligned.m16n8k16.row.col.f32.bf16.bf16.f32 "
        "{%0,%1,%2,%3}, {%4,%5,%6,%7}, {%8,%9}, {%0,%1,%2,%3};"
        : "+f"(d[0]), "+f"(d[1]), "+f"(d[2]), "+f"(d[3])
        : "r"(a[0]), "r"(a[1]), "r"(a[2]), "r"(a[3]), "r"(b[0]), "r"(b[1]));
}

__device__ __forceinline__ void ldsm4(uint32_t* r, uint32_t addr) {
    asm volatile("ldmatrix.sync.aligned.m8n8.x4.shared.b16 {%0,%1,%2,%3}, [%4];"
                 : "=r"(r[0]), "=r"(r[1]), "=r"(r[2]), "=r"(r[3]) : "r"(addr));
}

// pack two fp32 -> bf16x2 (hi), and residual (lo)
__device__ __forceinline__ uint32_t pack_hi(float a, float b) {
    __nv_bfloat162 h = __float22bfloat162_rn(make_float2(a, b));
    return *(uint32_t*)&h;
}
__device__ __forceinline__ uint32_t pack_lo(float a, float b, uint32_t hp) {
    __nv_bfloat162 h = *(__nv_bfloat162*)&hp;
    float2 hf = __bfloat1622float2(h);
    __nv_bfloat162 l = __float22bfloat162_rn(make_float2(a - hf.x, b - hf.y));
    return *(uint32_t*)&l;
}

__device__ __forceinline__ float silu_n(float x) {
    return 1.679177f * x / (1.f + expf(-x));
}

// ---------------------------------------------------------------------------
// Weight prep: W[K,128] fp32 -> bf16 hi/lo, n-major [n][K]
// ---------------------------------------------------------------------------
__global__ void prep_w_kernel(const float* __restrict__ W, int K,
                              __nv_bfloat16* __restrict__ hi, __nv_bfloat16* __restrict__ lo)
{
    int idx = blockIdx.x * blockDim.x + threadIdx.x;
    int total = (K >> 1) * 128;
    if (idx >= total) return;
    int n = idx & 127, k = (idx >> 7) << 1;
    float a = W[(size_t)k * 128 + n];
    float b = W[(size_t)(k + 1) * 128 + n];
    uint32_t hp = pack_hi(a, b);
    uint32_t lp = pack_lo(a, b, hp);
    *(uint32_t*)(hi + (size_t)n * K + k) = hp;
    *(uint32_t*)(lo + (size_t)n * K + k) = lp;
}

// ---------------------------------------------------------------------------
// fctp: out[m,w] = scale * sum_{u<128,v<8} X[m,u] Y[m,v] W[(u*8+v)*128 + w]
// Tile: 128 nodes x 128 cols, 8 warps (16 rows each). K=1024 in 16 chunks of 64.
// A fragments built directly in registers: A[m, u*8+v] = X[m,u]*Y[m,v];
// lane's v indices are fixed -> Y in registers, loop-invariant.
// 3-pass bf16 split: AhBh + AlBh + AhBl.
// ---------------------------------------------------------------------------
template<bool COMBINE>
__global__ __launch_bounds__(256)
void fctp_mma(const float* __restrict__ X, const float* __restrict__ Y,
              const __nv_bfloat16* __restrict__ Bh, const __nv_bfloat16* __restrict__ Bl,
              float* __restrict__ C, const float* __restrict__ SC,
              const float* __restrict__ ANG, int N)
{
    __shared__ __align__(16) float ys[128][8];
    __shared__ __align__(16) float xs[128][8];
    __shared__ __align__(16) __nv_bfloat16 bsh[128][72];   // +8 pad: conflict-free ldsm
    __shared__ __align__(16) __nv_bfloat16 bsl[128][72];

    const int tid = threadIdx.x, wid = tid >> 5, lane = tid & 31;
    const int r0 = blockIdx.x * 128;

    for (int i = tid; i < 1024; i += 256) {
        int n = i >> 3, v = i & 7, r = r0 + n;
        ys[n][v] = (r < N) ? Y[(size_t)r * 8 + v] : 0.f;
    }
    __syncthreads();

    const int q = lane >> 2, t4 = lane & 3;
    const int mr0 = wid * 16 + q, mr1 = mr0 + 8;
    const float ya0 = ys[mr0][2 * t4], ya1 = ys[mr0][2 * t4 + 1];
    const float yb0 = ys[mr1][2 * t4], yb1 = ys[mr1][2 * t4 + 1];

    float acc[16][4];
#pragma unroll
    for (int j = 0; j < 16; ++j)
#pragma unroll
        for (int i = 0; i < 4; ++i) acc[j][i] = 0.f;

    const uint32_t sbh = smem_u32(&bsh[0][0]);
    const uint32_t sbl = smem_u32(&bsl[0][0]);
    const int grp = lane >> 3, rw = lane & 7;

    for (int c = 0; c < 16; ++c) {
        __syncthreads();
        // stage x chunk [128][8] and B chunk [128 n][64 k] (hi+lo)
        for (int i = tid; i < 1024; i += 256) {
            int n = i >> 3, u = i & 7, r = r0 + n;
            xs[n][u] = (r < N) ? X[(size_t)r * 128 + c * 8 + u] : 0.f;
        }
        for (int i = tid; i < 1024; i += 256) {
            int n = i >> 3, seg = i & 7;
            *(uint4*)&bsh[n][seg * 8] = *(const uint4*)&Bh[(size_t)n * 1024 + c * 64 + seg * 8];
            *(uint4*)&bsl[n][seg * 8] = *(const uint4*)&Bl[(size_t)n * 1024 + c * 64 + seg * 8];
        }
        __syncthreads();

#pragma unroll
        for (int s = 0; s < 4; ++s) {
            // A fragment: rows mr0/mr1, k_local = s*16 + {2t4, 2t4+1, 2t4+8, 2t4+9}
            float x0a = xs[mr0][2 * s],     x0b = xs[mr1][2 * s];
            float x1a = xs[mr0][2 * s + 1], x1b = xs[mr1][2 * s + 1];
            uint32_t ah[4], al[4];
            {
                float p0 = x0a * ya0, p1 = x0a * ya1;
                ah[0] = pack_hi(p0, p1); al[0] = pack_lo(p0, p1, ah[0]);
            }
            {
                float p0 = x0b * yb0, p1 = x0b * yb1;
                ah[1] = pack_hi(p0, p1); al[1] = pack_lo(p0, p1, ah[1]);
            }
            {
                float p0 = x1a * ya0, p1 = x1a * ya1;
                ah[2] = pack_hi(p0, p1); al[2] = pack_lo(p0, p1, ah[2]);
            }
            {
                float p0 = x1b * yb0, p1 = x1b * yb1;
                ah[3] = pack_hi(p0, p1); al[3] = pack_lo(p0, p1, ah[3]);
            }
#pragma unroll
            for (int jj = 0; jj < 8; ++jj) {
                int nrow = 8 * (2 * jj + (grp >> 1)) + rw;
                int kcol = s * 16 + (grp & 1) * 8;
                uint32_t off = (uint32_t)(nrow * 72 + kcol) * 2;
                uint32_t bh[4], bl[4];
                ldsm4(bh, sbh + off);
                ldsm4(bl, sbl + off);
                mma16816(acc[2 * jj],     ah, bh);
                mma16816(acc[2 * jj + 1], ah, bh + 2);
                mma16816(acc[2 * jj],     al, bh);
                mma16816(acc[2 * jj + 1], al, bh + 2);
                mma16816(acc[2 * jj],     ah, bl);
                mma16816(acc[2 * jj + 1], ah, bl + 2);
            }
        }
    }

    // epilogue: C frag (row mr0/mr1, cols 8j + 2t4, +1)
    const float sk = 0.03125f;   // 1/sqrt(128*8)
    const int m0g = r0 + mr0, m1g = r0 + mr1;
    float ca0 = 1.f, sa0 = 0.f, ca1 = 1.f, sa1 = 0.f;
    if (COMBINE) {
        if (m0g < N) { float a = ANG[m0g]; ca0 = cosf(a); sa0 = sinf(a); }
        if (m1g < N) { float a = ANG[m1g]; ca1 = cosf(a); sa1 = sinf(a); }
    }
#pragma unroll
    for (int j = 0; j < 16; ++j) {
        int col = 8 * j + 2 * t4;
        if (m0g < N) {
            float2 v = make_float2(acc[j][0] * sk, acc[j][1] * sk);
            if (COMBINE) {
                const float* sp = SC + (size_t)m0g * 128 + col;
                v.x = ca0 * sp[0] + sa0 * v.x;
                v.y = ca0 * sp[1] + sa0 * v.y;
            }
            *(float2*)(C + (size_t)m0g * 128 + col) = v;
        }
        if (m1g < N) {
            float2 v = make_float2(acc[j][2] * sk, acc[j][3] * sk);
            if (COMBINE) {
                const float* sp = SC + (size_t)m1g * 128 + col;
                v.x = ca1 * sp[0] + sa1 * v.x;
                v.y = ca1 * sp[1] + sa1 * v.y;
            }
            *(float2*)(C + (size_t)m1g * 128 + col) = v;
        }
    }
}

// ---------------------------------------------------------------------------
// Fused edge MLP: wt = (SILU_NORM*silu(es@W1/8)) @ W2 / sqrt(128)
// Tile: 128 edges. GEMM1 K=64 -> silu in regs -> GEMM2 K=128 (C-frag == A-frag layout).
// ---------------------------------------------------------------------------
static const int EDGE_SMEM = (9216 * 4 + 17408 * 2) * 2;   // bytes = 143360

__global__ __launch_bounds__(256)
void edge_mlp_mma(const float* __restrict__ ES,
                  const __nv_bfloat16* __restrict__ B1h, const __nv_bfloat16* __restrict__ B1l,
                  const __nv_bfloat16* __restrict__ B2h, const __nv_bfloat16* __restrict__ B2l,
                  float* __restrict__ WT, int E)
{
    extern __shared__ __align__(16) __nv_bfloat16 sm[];
    __nv_bfloat16* ash = sm;              // [128][72]
    __nv_bfloat16* asl = sm + 9216;
    __nv_bfloat16* b1h = sm + 18432;      // [128][72]
    __nv_bfloat16* b1l = sm + 27648;
    __nv_bfloat16* b2h = sm + 36864;      // [128][136]
    __nv_bfloat16* b2l = sm + 54272;

    const int tid = threadIdx.x, wid = tid >> 5, lane = tid & 31;
    const int e0 = blockIdx.x * 128;

    // stage A1 (es tile, split) : 128 x 64, pairs
    for (int i = tid; i < 4096; i += 256) {
        int m = i >> 5, kp = (i & 31) * 2;
        int e = e0 + m;
        float v0 = 0.f, v1 = 0.f;
        if (e < E) {
            v0 = ES[(size_t)e * 64 + kp];
            v1 = ES[(size_t)e * 64 + kp + 1];
        }
        uint32_t hp = pack_hi(v0, v1);
        uint32_t lp = pack_lo(v0, v1, hp);
        *(uint32_t*)(ash + m * 72 + kp) = hp;
        *(uint32_t*)(asl + m * 72 + kp) = lp;
    }
    // stage B1 [128][64], B2 [128][128]
    for (int i = tid; i < 1024; i += 256) {
        int n = i >> 3, seg = i & 7;
        *(uint4*)(b1h + n * 72 + seg * 8) = *(const uint4*)(B1h + (size_t)n * 64 + seg * 8);
        *(uint4*)(b1l + n * 72 + seg * 8) = *(const uint4*)(B1l + (size_t)n * 64 + seg * 8);
    }
    for (int i = tid; i < 2048; i += 256) {
        int n = i >> 4, seg = i & 15;
        *(uint4*)(b2h + n * 136 + seg * 8) = *(const uint4*)(B2h + (size_t)n * 128 + seg * 8);
        *(uint4*)(b2l + n * 136 + seg * 8) = *(const uint4*)(B2l + (size_t)n * 128 + seg * 8);
    }
    __syncthreads();

    const int q = lane >> 2, t4 = lane & 3;
    const int grp = lane >> 3, rw = lane & 7;
    const uint32_t sa_h = smem_u32(ash), sa_l = smem_u32(asl);
    const uint32_t s1h = smem_u32(b1h), s1l = smem_u32(b1l);
    const uint32_t s2h = smem_u32(b2h), s2l = smem_u32(b2l);

    float acc1[16][4];
#pragma unroll
    for (int j = 0; j < 16; ++j)
#pragma unroll
        for (int i = 0; i < 4; ++i) acc1[j][i] = 0.f;

    // GEMM1: [128x64] @ [64x128]
#pragma unroll
    for (int s = 0; s < 4; ++s) {
        int mrow = wid * 16 + rw + (grp & 1) * 8;
        int kcol = s * 16 + (grp >> 1) * 8;
        uint32_t aoffs = (uint32_t)(mrow * 72 + kcol) * 2;
        uint32_t ah[4], al[4];
        ldsm4(ah, sa_h + aoffs);
        ldsm4(al, sa_l + aoffs);
#pragma unroll
        for (int jj = 0; jj < 8; ++jj) {
            int nrow = 8 * (2 * jj + (grp >> 1)) + rw;
            int kc = s * 16 + (grp & 1) * 8;
            uint32_t off = (uint32_t)(nrow * 72 + kc) * 2;
            uint32_t bh[4], bl[4];
            ldsm4(bh, s1h + off);
            ldsm4(bl, s1l + off);
            mma16816(acc1[2 * jj],     ah, bh);
            mma16816(acc1[2 * jj + 1], ah, bh + 2);
            mma16816(acc1[2 * jj],     al, bh);
            mma16816(acc1[2 * jj + 1], al, bh + 2);
            mma16816(acc1[2 * jj],     ah, bl);
            mma16816(acc1[2 * jj + 1], ah, bl + 2);
        }
    }

    // silu (with 1/sqrt(64) fan-in scale)
#pragma unroll
    for (int j = 0; j < 16; ++j)
#pragma unroll
        for (int i = 0; i < 4; ++i) acc1[j][i] = silu_n(acc1[j][i] * 0.125f);

    float acc2[16][4];
#pragma unroll
    for (int j = 0; j < 16; ++j)
#pragma unroll
        for (int i = 0; i < 4; ++i) acc2[j][i] = 0.f;

    // GEMM2: A2 fragments directly from acc1 (C-frag layout == A-frag layout)
#pragma unroll
    for (int s = 0; s < 8; ++s) {
        uint32_t ah[4], al[4];
        ah[0] = pack_hi(acc1[2 * s][0],     acc1[2 * s][1]);
        al[0] = pack_lo(acc1[2 * s][0],     acc1[2 * s][1],     ah[0]);
        ah[1] = pack_hi(acc1[2 * s][2],     acc1[2 * s][3]);
        al[1] = pack_lo(acc1[2 * s][2],     acc1[2 * s][3],     ah[1]);
        ah[2] = pack_hi(acc1[2 * s + 1][0], acc1[2 * s + 1][1]);
        al[2] = pack_lo(acc1[2 * s + 1][0], acc1[2 * s + 1][1], ah[2]);
        ah[3] = pack_hi(acc1[2 * s + 1][2], acc1[2 * s + 1][3]);
        al[3] = pack_lo(acc1[2 * s + 1][2], acc1[2 * s + 1][3], ah[3]);
#pragma unroll
        for (int jj = 0; jj < 8; ++jj) {
            int nrow = 8 * (2 * jj + (grp >> 1)) + rw;
            int kc = s * 16 + (grp & 1) * 8;
            uint32_t off = (uint32_t)(nrow * 136 + kc) * 2;
            uint32_t bh[4], bl[4];
            ldsm4(bh, s2h + off);
            ldsm4(bl, s2l + off);
            mma16816(acc2[2 * jj],     ah, bh);
            mma16816(acc2[2 * jj + 1], ah, bh + 2);
            mma16816(acc2[2 * jj],     al, bh);
            mma16816(acc2[2 * jj + 1], al, bh + 2);
            mma16816(acc2[2 * jj],     ah, bl);
            mma16816(acc2[2 * jj + 1], ah, bl + 2);
        }
    }

    // store wt
    const float sk = 0.08838834764831845f;   // 1/sqrt(128)
    const int er0 = e0 + wid * 16 + q, er1 = er0 + 8;
#pragma unroll
    for (int j = 0; j < 16; ++j) {
        int col = 8 * j + 2 * t4;
        if (er0 < E)
            *(float2*)(WT + (size_t)er0 * 128 + col) = make_float2(acc2[j][0] * sk, acc2[j][1] * sk);
        if (er1 < E)
            *(float2*)(WT + (size_t)er1 * 128 + col) = make_float2(acc2[j][2] * sk, acc2[j][3] * sk);
    }
}

// ---------------------------------------------------------------------------
// Edge scatter: rf[dst] += wt[e] * sf[src] * eattr[e] / sqrt(32); warp/edge
// ---------------------------------------------------------------------------
__global__ void scatter_kernel(const float* __restrict__ wt, const float* __restrict__ sf,
                               const int* __restrict__ src, const int* __restrict__ dst,
                               const float* __restrict__ eattr, float* __restrict__ rf, int E)
{
    int gw   = (blockIdx.x * blockDim.x + threadIdx.x) >> 5;
    int lane = threadIdx.x & 31;
    if (gw >= E) return;
    int s = src[gw], d = dst[gw];
    float ea = eattr[gw] * 0.17677669529663687f;   // 1/sqrt(32)
    float4 w4 = ((const float4*)(wt + (size_t)gw * 128))[lane];
    float4 s4 = ((const float4*)(sf + (size_t)s  * 128))[lane];
    float* o = rf + (size_t)d * 128 + lane * 4;
    atomicAdd(o + 0, w4.x * s4.x * ea);
    atomicAdd(o + 1, w4.y * s4.y * ea);
    atomicAdd(o + 2, w4.z * s4.z * ea);
    atomicAdd(o + 3, w4.w * s4.w * ea);
}

// ---------------------------------------------------------------------------
// Angle: ang[n] = 0.1/32 * sum_{u,v} rf[n,u] rattr[n,v] W3[u*8+v]; warp/node
// ---------------------------------------------------------------------------
__global__ void angle_kernel(const float* __restrict__ RF, const float* __restrict__ RA,
                             const float* __restrict__ W3, float* __restrict__ ANG, int N)
{
    int gw   = (blockIdx.x * blockDim.x + threadIdx.x) >> 5;
    int lane = threadIdx.x & 31;
    if (gw >= N) return;
    float ya[8];
#pragma unroll
    for (int v = 0; v < 8; ++v) ya[v] = RA[(size_t)gw * 8 + v];
    float sacc = 0.f;
#pragma unroll
    for (int uu = 0; uu < 4; ++uu) {
        int u = lane + uu * 32;
        float xv = RF[(size_t)gw * 128 + u];
#pragma unroll
        for (int v = 0; v < 8; ++v) sacc += xv * ya[v] * W3[u * 8 + v];
    }
#pragma unroll
    for (int off = 16; off; off >>= 1) sacc += __shfl_xor_sync(0xffffffffu, sacc, off);
    if (lane == 0) ANG[gw] = 0.003125f * sacc;   // 0.1 / 32
}

// ---------------------------------------------------------------------------
extern "C" void kernel_launch(void* const* d_in, const int* in_sizes, int n_in,
                              void* d_out, int out_size)
{
    const float* sender_input   = (const float*)d_in[0];
    const float* sender_attr    = (const float*)d_in[1];
    const float* receiver_input = (const float*)d_in[2];
    const float* receiver_attr  = (const float*)d_in[3];
    const int*   edge_src       = (const int*)  d_in[4];
    const int*   edge_dst       = (const int*)  d_in[5];
    const float* edge_attr      = (const float*)d_in[6];
    const float* edge_scalars   = (const float*)d_in[7];
    const float* W_sc           = (const float*)d_in[8];
    const float* W_lin1         = (const float*)d_in[9];
    const float* W_fc1          = (const float*)d_in[10];
    const float* W_fc2          = (const float*)d_in[11];
    const float* W_lin2         = (const float*)d_in[12];
    const float* W_lin3         = (const float*)d_in[13];

    const int Ns = in_sizes[0] / 128;
    const int Nr = in_sizes[2] / 128;
    const int E  = in_sizes[4];

    float *wt_p, *sf_p, *sc_p, *rf_p, *ang_p;
    uint8_t (*wp)[262144];
    cudaGetSymbolAddress((void**)&wt_p,  g_wt);
    cudaGetSymbolAddress((void**)&sf_p,  g_sf);
    cudaGetSymbolAddress((void**)&sc_p,  g_sc);
    cudaGetSymbolAddress((void**)&rf_p,  g_rf);
    cudaGetSymbolAddress((void**)&ang_p, g_ang);
    cudaGetSymbolAddress((void**)&wp,    g_wp);

    cudaFuncSetAttribute(edge_mlp_mma, cudaFuncAttributeMaxDynamicSharedMemorySize, EDGE_SMEM);

    // --- weight prep ---
    prep_w_kernel<<<16,  256>>>(W_fc1,  64,   (__nv_bfloat16*)wp[0], (__nv_bfloat16*)wp[1]);
    prep_w_kernel<<<32,  256>>>(W_fc2,  128,  (__nv_bfloat16*)wp[2], (__nv_bfloat16*)wp[3]);
    prep_w_kernel<<<256, 256>>>(W_lin1, 1024, (__nv_bfloat16*)wp[4], (__nv_bfloat16*)wp[5]);
    prep_w_kernel<<<256, 256>>>(W_sc,   1024, (__nv_bfloat16*)wp[6], (__nv_bfloat16*)wp[7]);
    prep_w_kernel<<<256, 256>>>(W_lin2, 1024, (__nv_bfloat16*)wp[8], (__nv_bfloat16*)wp[9]);

    // --- fused edge MLP ---
    edge_mlp_mma<<<(E + 127) / 128, 256, EDGE_SMEM>>>(
        edge_scalars,
        (const __nv_bfloat16*)wp[0], (const __nv_bfloat16*)wp[1],
        (const __nv_bfloat16*)wp[2], (const __nv_bfloat16*)wp[3],
        wt_p, E);

    // --- node fctps ---
    fctp_mma<false><<<(Ns + 127) / 128, 256>>>(sender_input, sender_attr,
        (const __nv_bfloat16*)wp[4], (const __nv_bfloat16*)wp[5],
        sf_p, nullptr, nullptr, Ns);
    fctp_mma<false><<<(Nr + 127) / 128, 256>>>(receiver_input, receiver_attr,
        (const __nv_bfloat16*)wp[6], (const __nv_bfloat16*)wp[7],
        sc_p, nullptr, nullptr, Nr);

    // --- scatter ---
    cudaMemsetAsync(rf_p, 0, (size_t)Nr * 128 * sizeof(float));
    scatter_kernel<<<((long long)E * 32 + 255) / 256, 256>>>(wt_p, sf_p, edge_src, edge_dst,
                                                             edge_attr, rf_p, E);

    // --- angle + final fctp with gating epilogue ---
    angle_kernel<<<((long long)Nr * 32 + 255) / 256, 256>>>(rf_p, receiver_attr, W_lin3, ang_p, Nr);
    fctp_mma<true><<<(Nr + 127) / 128, 256>>>(rf_p, receiver_attr,
        (const __nv_bfloat16*)wp[8], (const __nv_bfloat16*)wp[9],
        (float*)d_out, sc_p, ang_p, Nr);
}

// round 4
// speedup vs baseline: 2.4964x; 1.0480x over previous
#include <cuda_runtime.h>
#include <cuda_bf16.h>
#include <math.h>
#include <stdint.h>

// ---------------------------------------------------------------------------
// Shapes: Ns=Nr=100000, E=600000, D=128, A=8, S=64, H=128
// ---------------------------------------------------------------------------
#define MAX_E 600000
#define MAX_N 100000

// Scratch (__device__ globals; allocation-free rule)
__device__ float g_sf [(size_t)MAX_N * 128];   // sender features
__device__ float g_sc [(size_t)MAX_N * 128];   // receiver self connection
__device__ float g_rf [(size_t)MAX_N * 128];   // scattered receiver features
__device__ float g_ang[(size_t)MAX_N];         // receiver angle
// Prepped weights, bf16 n-major [128 n][K k]; slots of 256KB (max K=1024)
// ids: 0=fc1_h 1=fc1_l 2=fc2_h 3=fc2_l 4=lin1_h 5=lin1_l 6=sc_h 7=sc_l 8=lin2_h 9=lin2_l
__device__ __align__(1024) uint8_t g_wp[10][262144];

// ---------------------------------------------------------------------------
// mma.sync / ldmatrix / cp.async helpers (sm_80+, no arch-a gating)
// ---------------------------------------------------------------------------
__device__ __forceinline__ uint32_t smem_u32(const void* p) {
    uint32_t a;
    asm("{ .reg .u64 t; cvta.to.shared.u64 t, %1; cvt.u32.u64 %0, t; }" : "=r"(a) : "l"(p));
    return a;
}

__device__ __forceinline__ void mma16816(float* d, const uint32_t* a, const uint32_t* b) {
    asm volatile(
        "mma.sync.aligned.m16n8k16.row.col.f32.bf16.bf16.f32 "
        "{%0,%1,%2,%3}, {%4,%5,%6,%7}, {%8,%9}, {%0,%1,%2,%3};"
        : "+f"(d[0]), "+f"(d[1]), "+f"(d[2]), "+f"(d[3])
        : "r"(a[0]), "r"(a[1]), "r"(a[2]), "r"(a[3]), "r"(b[0]), "r"(b[1]));
}

__device__ __forceinline__ void ldsm4(uint32_t* r, uint32_t addr) {
    asm volatile("ldmatrix.sync.aligned.m8n8.x4.shared.b16 {%0,%1,%2,%3}, [%4];"
                 : "=r"(r[0]), "=r"(r[1]), "=r"(r[2]), "=r"(r[3]) : "r"(addr));
}

__device__ __forceinline__ void cp16(uint32_t s, const void* g, int bytes) {
    asm volatile("cp.async.cg.shared.global [%0], [%1], 16, %2;"
                 :: "r"(s), "l"(g), "r"(bytes) : "memory");
}
#define CP_COMMIT() asm volatile("cp.async.commit_group;" ::: "memory")
#define CP_WAIT0()  asm volatile("cp.async.wait_group 0;" ::: "memory")

// pack two fp32 -> bf16x2 (hi), and residual (lo)
__device__ __forceinline__ uint32_t pack_hi(float a, float b) {
    __nv_bfloat162 h = __float22bfloat162_rn(make_float2(a, b));
    return *(uint32_t*)&h;
}
__device__ __forceinline__ uint32_t pack_lo(float a, float b, uint32_t hp) {
    __nv_bfloat162 h = *(__nv_bfloat162*)&hp;
    float2 hf = __bfloat1622float2(h);
    __nv_bfloat162 l = __float22bfloat162_rn(make_float2(a - hf.x, b - hf.y));
    return *(uint32_t*)&l;
}

__device__ __forceinline__ float silu_n(float x) {
    return 1.679177f * x / (1.f + expf(-x));
}

// ---------------------------------------------------------------------------
// Weight prep: W[K,128] fp32 -> bf16 hi/lo, n-major [n][K]
// ---------------------------------------------------------------------------
__global__ void prep_w_kernel(const float* __restrict__ W, int K,
                              __nv_bfloat16* __restrict__ hi, __nv_bfloat16* __restrict__ lo)
{
    int idx = blockIdx.x * blockDim.x + threadIdx.x;
    int total = (K >> 1) * 128;
    if (idx >= total) return;
    int n = idx & 127, k = (idx >> 7) << 1;
    float a = W[(size_t)k * 128 + n];
    float b = W[(size_t)(k + 1) * 128 + n];
    uint32_t hp = pack_hi(a, b);
    uint32_t lp = pack_lo(a, b, hp);
    *(uint32_t*)(hi + (size_t)n * K + k) = hp;
    *(uint32_t*)(lo + (size_t)n * K + k) = lp;
}

// ---------------------------------------------------------------------------
// fctp: out[m,w] = scale * sum_{u<128,v<8} X[m,u] Y[m,v] W[(u*8+v)*128 + w]
// Tile: 128 nodes x 128 cols. 8 warps, each 32 rows x 64 cols (halves B ldsm
// traffic vs 16x128). K=1024 in 16 chunks of 64, cp.async double-buffered.
// A fragments built in registers: A[m, u*8+v] = X[m,u]*Y[m,v].
// 3-pass bf16 split: AhBh + AlBh + AhBl.
// ---------------------------------------------------------------------------
static const int FCTP_SMEM = 86016;   // ys 4K + xs 8K + bsh 36K + bsl 36K

template<bool COMBINE>
__global__ __launch_bounds__(256)
void fctp_mma(const float* __restrict__ X, const float* __restrict__ Y,
              const __nv_bfloat16* __restrict__ Bh, const __nv_bfloat16* __restrict__ Bl,
              float* __restrict__ C, const float* __restrict__ SC,
              const float* __restrict__ ANG, int N)
{
    extern __shared__ __align__(16) uint8_t smraw[];
    float* ys = (float*)smraw;                                   // [128][8]
    float* xs = (float*)(smraw + 4096);                          // [2][128][8]
    __nv_bfloat16* bsh = (__nv_bfloat16*)(smraw + 12288);        // [2][128][72]
    __nv_bfloat16* bsl = (__nv_bfloat16*)(smraw + 49152);        // [2][128][72]

    const int tid = threadIdx.x, wid = tid >> 5, lane = tid & 31;
    const int r0 = blockIdx.x * 128;
    const int q = lane >> 2, t4 = lane & 3, grp = lane >> 3, rw = lane & 7;
    const int mw = (wid & 3) * 32, nw = (wid >> 2) * 64;

    const uint32_t xs_a  = smem_u32(xs);
    const uint32_t bsh_a = smem_u32(bsh);
    const uint32_t bsl_a = smem_u32(bsl);

    for (int i = tid; i < 1024; i += 256) {
        int n = i >> 3, v = i & 7, r = r0 + n;
        ys[i] = (r < N) ? Y[(size_t)r * 8 + v] : 0.f;
    }

    auto stage = [&](int c, int b) {
        {   // xs: one 16B cp per thread (128 rows x 2 halves)
            int n = tid >> 1, h = tid & 1, r = r0 + n;
            int rc = (r < N) ? r : 0;
            cp16(xs_a + (uint32_t)(b * 1024 + n * 8 + h * 4) * 4,
                 X + (size_t)rc * 128 + c * 8 + h * 4, (r < N) ? 16 : 0);
        }
#pragma unroll
        for (int t = 0; t < 4; ++t) {   // B hi+lo: [128 n][64 k]
            int idx = tid + t * 256;
            int n = idx >> 3, seg = idx & 7;
            uint32_t so = (uint32_t)(b * 9216 + n * 72 + seg * 8) * 2;
            cp16(bsh_a + so, Bh + (size_t)n * 1024 + c * 64 + seg * 8, 16);
            cp16(bsl_a + so, Bl + (size_t)n * 1024 + c * 64 + seg * 8, 16);
        }
    };

    float acc[2][8][4];
#pragma unroll
    for (int mg = 0; mg < 2; ++mg)
#pragma unroll
        for (int j = 0; j < 8; ++j)
#pragma unroll
            for (int i = 0; i < 4; ++i) acc[mg][j][i] = 0.f;

    float ya[4][2];

    stage(0, 0); CP_COMMIT();

    for (int c = 0; c < 16; ++c) {
        CP_WAIT0();
        __syncthreads();
        if (c == 0) {
#pragma unroll
            for (int g = 0; g < 4; ++g) {
                ya[g][0] = ys[(mw + 8 * g + q) * 8 + 2 * t4];
                ya[g][1] = ys[(mw + 8 * g + q) * 8 + 2 * t4 + 1];
            }
        }
        if (c < 15) { stage(c + 1, (c + 1) & 1); CP_COMMIT(); }

        const int b = c & 1;
        const float* xb = xs + b * 1024;
#pragma unroll
        for (int s = 0; s < 4; ++s) {
            uint32_t ah[2][4], al[2][4];
#pragma unroll
            for (int mg = 0; mg < 2; ++mg) {
                int rA = mw + 16 * mg + q, rB = rA + 8;
                float x0a = xb[rA * 8 + 2 * s], x1a = xb[rA * 8 + 2 * s + 1];
                float x0b = xb[rB * 8 + 2 * s], x1b = xb[rB * 8 + 2 * s + 1];
                float ya0 = ya[2 * mg][0],     ya1 = ya[2 * mg][1];
                float yb0 = ya[2 * mg + 1][0], yb1 = ya[2 * mg + 1][1];
                float p0, p1;
                p0 = x0a * ya0; p1 = x0a * ya1;
                ah[mg][0] = pack_hi(p0, p1); al[mg][0] = pack_lo(p0, p1, ah[mg][0]);
                p0 = x0b * yb0; p1 = x0b * yb1;
                ah[mg][1] = pack_hi(p0, p1); al[mg][1] = pack_lo(p0, p1, ah[mg][1]);
                p0 = x1a * ya0; p1 = x1a * ya1;
                ah[mg][2] = pack_hi(p0, p1); al[mg][2] = pack_lo(p0, p1, ah[mg][2]);
                p0 = x1b * yb0; p1 = x1b * yb1;
                ah[mg][3] = pack_hi(p0, p1); al[mg][3] = pack_lo(p0, p1, ah[mg][3]);
            }
#pragma unroll
            for (int jj = 0; jj < 4; ++jj) {
                int nrow = nw + 8 * (2 * jj + (grp >> 1)) + rw;
                int kcol = s * 16 + (grp & 1) * 8;
                uint32_t off = (uint32_t)(b * 9216 + nrow * 72 + kcol) * 2;
                uint32_t bh[4], bl[4];
                ldsm4(bh, bsh_a + off);
                ldsm4(bl, bsl_a + off);
#pragma unroll
                for (int mg = 0; mg < 2; ++mg) {
                    mma16816(acc[mg][2 * jj],     ah[mg], bh);
                    mma16816(acc[mg][2 * jj + 1], ah[mg], bh + 2);
                    mma16816(acc[mg][2 * jj],     al[mg], bh);
                    mma16816(acc[mg][2 * jj + 1], al[mg], bh + 2);
                    mma16816(acc[mg][2 * jj],     ah[mg], bl);
                    mma16816(acc[mg][2 * jj + 1], ah[mg], bl + 2);
                }
            }
        }
    }

    // epilogue
    const float sk = 0.03125f;   // 1/sqrt(128*8)
#pragma unroll
    for (int mg = 0; mg < 2; ++mg) {
#pragma unroll
        for (int h = 0; h < 2; ++h) {
            int m = r0 + mw + 16 * mg + 8 * h + q;
            if (m >= N) continue;
            float ca = 1.f, sa = 0.f;
            if (COMBINE) { float a = ANG[m]; ca = cosf(a); sa = sinf(a); }
#pragma unroll
            for (int j = 0; j < 8; ++j) {
                int col = nw + 8 * j + 2 * t4;
                float2 v = make_float2(acc[mg][j][2 * h] * sk, acc[mg][j][2 * h + 1] * sk);
                if (COMBINE) {
                    const float* sp = SC + (size_t)m * 128 + col;
                    v.x = ca * sp[0] + sa * v.x;
                    v.y = ca * sp[1] + sa * v.y;
                }
                *(float2*)(C + (size_t)m * 128 + col) = v;
            }
        }
    }
}

// ---------------------------------------------------------------------------
// Fused edge MLP + scatter:
//   wt = (SILU_NORM*silu(es@W1/8)) @ W2 / sqrt(128)   (kept in registers)
//   rf[dst] += wt * sf[src] * eattr / sqrt(32)        (atomic epilogue)
// Tile: 128 edges. GEMM1 K=64 -> silu in regs -> GEMM2 K=128.
// ---------------------------------------------------------------------------
static const int EDGE_SMEM = (9216 * 4 + 17408 * 2) * 2;   // 143360 B

__global__ __launch_bounds__(256)
void edge_mlp_mma(const float* __restrict__ ES,
                  const __nv_bfloat16* __restrict__ B1h, const __nv_bfloat16* __restrict__ B1l,
                  const __nv_bfloat16* __restrict__ B2h, const __nv_bfloat16* __restrict__ B2l,
                  const float* __restrict__ SF, const int* __restrict__ SRC,
                  const int* __restrict__ DST, const float* __restrict__ EA,
                  float* __restrict__ RF, int E)
{
    extern __shared__ __align__(16) __nv_bfloat16 sm[];
    __nv_bfloat16* ash = sm;              // [128][72]
    __nv_bfloat16* asl = sm + 9216;
    __nv_bfloat16* b1h = sm + 18432;      // [128][72]
    __nv_bfloat16* b1l = sm + 27648;
    __nv_bfloat16* b2h = sm + 36864;      // [128][136]
    __nv_bfloat16* b2l = sm + 54272;

    const int tid = threadIdx.x, wid = tid >> 5, lane = tid & 31;
    const int e0 = blockIdx.x * 128;

    // stage A1 (es tile, split)
    for (int i = tid; i < 4096; i += 256) {
        int m = i >> 5, kp = (i & 31) * 2;
        int e = e0 + m;
        float v0 = 0.f, v1 = 0.f;
        if (e < E) {
            v0 = ES[(size_t)e * 64 + kp];
            v1 = ES[(size_t)e * 64 + kp + 1];
        }
        uint32_t hp = pack_hi(v0, v1);
        uint32_t lp = pack_lo(v0, v1, hp);
        *(uint32_t*)(ash + m * 72 + kp) = hp;
        *(uint32_t*)(asl + m * 72 + kp) = lp;
    }
    for (int i = tid; i < 1024; i += 256) {
        int n = i >> 3, seg = i & 7;
        *(uint4*)(b1h + n * 72 + seg * 8) = *(const uint4*)(B1h + (size_t)n * 64 + seg * 8);
        *(uint4*)(b1l + n * 72 + seg * 8) = *(const uint4*)(B1l + (size_t)n * 64 + seg * 8);
    }
    for (int i = tid; i < 2048; i += 256) {
        int n = i >> 4, seg = i & 15;
        *(uint4*)(b2h + n * 136 + seg * 8) = *(const uint4*)(B2h + (size_t)n * 128 + seg * 8);
        *(uint4*)(b2l + n * 136 + seg * 8) = *(const uint4*)(B2l + (size_t)n * 128 + seg * 8);
    }
    __syncthreads();

    const int q = lane >> 2, t4 = lane & 3;
    const int grp = lane >> 3, rw = lane & 7;
    const uint32_t sa_h = smem_u32(ash), sa_l = smem_u32(asl);
    const uint32_t s1h = smem_u32(b1h), s1l = smem_u32(b1l);
    const uint32_t s2h = smem_u32(b2h), s2l = smem_u32(b2l);

    float acc1[16][4];
#pragma unroll
    for (int j = 0; j < 16; ++j)
#pragma unroll
        for (int i = 0; i < 4; ++i) acc1[j][i] = 0.f;

    // GEMM1: [128x64] @ [64x128]
#pragma unroll
    for (int s = 0; s < 4; ++s) {
        int mrow = wid * 16 + rw + (grp & 1) * 8;
        int kcol = s * 16 + (grp >> 1) * 8;
        uint32_t aoffs = (uint32_t)(mrow * 72 + kcol) * 2;
        uint32_t ah[4], al[4];
        ldsm4(ah, sa_h + aoffs);
        ldsm4(al, sa_l + aoffs);
#pragma unroll
        for (int jj = 0; jj < 8; ++jj) {
            int nrow = 8 * (2 * jj + (grp >> 1)) + rw;
            int kc = s * 16 + (grp & 1) * 8;
            uint32_t off = (uint32_t)(nrow * 72 + kc) * 2;
            uint32_t bh[4], bl[4];
            ldsm4(bh, s1h + off);
            ldsm4(bl, s1l + off);
            mma16816(acc1[2 * jj],     ah, bh);
            mma16816(acc1[2 * jj + 1], ah, bh + 2);
            mma16816(acc1[2 * jj],     al, bh);
            mma16816(acc1[2 * jj + 1], al, bh + 2);
            mma16816(acc1[2 * jj],     ah, bl);
            mma16816(acc1[2 * jj + 1], ah, bl + 2);
        }
    }

    // silu (1/sqrt(64) fan-in scale)
#pragma unroll
    for (int j = 0; j < 16; ++j)
#pragma unroll
        for (int i = 0; i < 4; ++i) acc1[j][i] = silu_n(acc1[j][i] * 0.125f);

    float acc2[16][4];
#pragma unroll
    for (int j = 0; j < 16; ++j)
#pragma unroll
        for (int i = 0; i < 4; ++i) acc2[j][i] = 0.f;

    // GEMM2: A2 fragments directly from acc1 (C-frag layout == A-frag layout)
#pragma unroll
    for (int s = 0; s < 8; ++s) {
        uint32_t ah[4], al[4];
        ah[0] = pack_hi(acc1[2 * s][0],     acc1[2 * s][1]);
        al[0] = pack_lo(acc1[2 * s][0],     acc1[2 * s][1],     ah[0]);
        ah[1] = pack_hi(acc1[2 * s][2],     acc1[2 * s][3]);
        al[1] = pack_lo(acc1[2 * s][2],     acc1[2 * s][3],     ah[1]);
        ah[2] = pack_hi(acc1[2 * s + 1][0], acc1[2 * s + 1][1]);
        al[2] = pack_lo(acc1[2 * s + 1][0], acc1[2 * s + 1][1], ah[2]);
        ah[3] = pack_hi(acc1[2 * s + 1][2], acc1[2 * s + 1][3]);
        al[3] = pack_lo(acc1[2 * s + 1][2], acc1[2 * s + 1][3], ah[3]);
#pragma unroll
        for (int jj = 0; jj < 8; ++jj) {
            int nrow = 8 * (2 * jj + (grp >> 1)) + rw;
            int kc = s * 16 + (grp & 1) * 8;
            uint32_t off = (uint32_t)(nrow * 136 + kc) * 2;
            uint32_t bh[4], bl[4];
            ldsm4(bh, s2h + off);
            ldsm4(bl, s2l + off);
            mma16816(acc2[2 * jj],     ah, bh);
            mma16816(acc2[2 * jj + 1], ah, bh + 2);
            mma16816(acc2[2 * jj],     al, bh);
            mma16816(acc2[2 * jj + 1], al, bh + 2);
            mma16816(acc2[2 * jj],     ah, bl);
            mma16816(acc2[2 * jj + 1], ah, bl + 2);
        }
    }

    // fused scatter epilogue: rf[dst] += wt * sf[src] * eattr / sqrt(32)
    const float sk = 0.08838834764831845f;   // 1/sqrt(128)
#pragma unroll
    for (int h = 0; h < 2; ++h) {
        int er = e0 + wid * 16 + 8 * h + q;
        if (er >= E) continue;
        int sidx = SRC[er], didx = DST[er];
        float ea = EA[er] * 0.17677669529663687f * sk;   // fold 1/sqrt(32) * 1/sqrt(128)
        const float* sfr = SF + (size_t)sidx * 128;
        float* rfr = RF + (size_t)didx * 128;
#pragma unroll
        for (int j = 0; j < 16; ++j) {
            int col = 8 * j + 2 * t4;
            float2 s2 = *(const float2*)(sfr + col);
            atomicAdd(rfr + col,     acc2[j][2 * h]     * ea * s2.x);
            atomicAdd(rfr + col + 1, acc2[j][2 * h + 1] * ea * s2.y);
        }
    }
}

// ---------------------------------------------------------------------------
// Angle: ang[n] = 0.1/32 * sum_{u,v} rf[n,u] rattr[n,v] W3[u*8+v]; warp/node
// ---------------------------------------------------------------------------
__global__ void angle_kernel(const float* __restrict__ RF, const float* __restrict__ RA,
                             const float* __restrict__ W3, float* __restrict__ ANG, int N)
{
    int gw   = (blockIdx.x * blockDim.x + threadIdx.x) >> 5;
    int lane = threadIdx.x & 31;
    if (gw >= N) return;
    float ya[8];
#pragma unroll
    for (int v = 0; v < 8; ++v) ya[v] = RA[(size_t)gw * 8 + v];
    float sacc = 0.f;
#pragma unroll
    for (int uu = 0; uu < 4; ++uu) {
        int u = lane + uu * 32;
        float xv = RF[(size_t)gw * 128 + u];
#pragma unroll
        for (int v = 0; v < 8; ++v) sacc += xv * ya[v] * W3[u * 8 + v];
    }
#pragma unroll
    for (int off = 16; off; off >>= 1) sacc += __shfl_xor_sync(0xffffffffu, sacc, off);
    if (lane == 0) ANG[gw] = 0.003125f * sacc;   // 0.1 / 32
}

// ---------------------------------------------------------------------------
extern "C" void kernel_launch(void* const* d_in, const int* in_sizes, int n_in,
                              void* d_out, int out_size)
{
    const float* sender_input   = (const float*)d_in[0];
    const float* sender_attr    = (const float*)d_in[1];
    const float* receiver_input = (const float*)d_in[2];
    const float* receiver_attr  = (const float*)d_in[3];
    const int*   edge_src       = (const int*)  d_in[4];
    const int*   edge_dst       = (const int*)  d_in[5];
    const float* edge_attr      = (const float*)d_in[6];
    const float* edge_scalars   = (const float*)d_in[7];
    const float* W_sc           = (const float*)d_in[8];
    const float* W_lin1         = (const float*)d_in[9];
    const float* W_fc1          = (const float*)d_in[10];
    const float* W_fc2          = (const float*)d_in[11];
    const float* W_lin2         = (const float*)d_in[12];
    const float* W_lin3         = (const float*)d_in[13];

    const int Ns = in_sizes[0] / 128;
    const int Nr = in_sizes[2] / 128;
    const int E  = in_sizes[4];

    float *sf_p, *sc_p, *rf_p, *ang_p;
    uint8_t (*wp)[262144];
    cudaGetSymbolAddress((void**)&sf_p,  g_sf);
    cudaGetSymbolAddress((void**)&sc_p,  g_sc);
    cudaGetSymbolAddress((void**)&rf_p,  g_rf);
    cudaGetSymbolAddress((void**)&ang_p, g_ang);
    cudaGetSymbolAddress((void**)&wp,    g_wp);

    cudaFuncSetAttribute(edge_mlp_mma,   cudaFuncAttributeMaxDynamicSharedMemorySize, EDGE_SMEM);
    cudaFuncSetAttribute(fctp_mma<false>, cudaFuncAttributeMaxDynamicSharedMemorySize, FCTP_SMEM);
    cudaFuncSetAttribute(fctp_mma<true>,  cudaFuncAttributeMaxDynamicSharedMemorySize, FCTP_SMEM);

    // --- weight prep ---
    prep_w_kernel<<<16,  256>>>(W_fc1,  64,   (__nv_bfloat16*)wp[0], (__nv_bfloat16*)wp[1]);
    prep_w_kernel<<<32,  256>>>(W_fc2,  128,  (__nv_bfloat16*)wp[2], (__nv_bfloat16*)wp[3]);
    prep_w_kernel<<<256, 256>>>(W_lin1, 1024, (__nv_bfloat16*)wp[4], (__nv_bfloat16*)wp[5]);
    prep_w_kernel<<<256, 256>>>(W_sc,   1024, (__nv_bfloat16*)wp[6], (__nv_bfloat16*)wp[7]);
    prep_w_kernel<<<256, 256>>>(W_lin2, 1024, (__nv_bfloat16*)wp[8], (__nv_bfloat16*)wp[9]);

    // --- sender features (needed by fused edge MLP) ---
    fctp_mma<false><<<(Ns + 127) / 128, 256, FCTP_SMEM>>>(sender_input, sender_attr,
        (const __nv_bfloat16*)wp[4], (const __nv_bfloat16*)wp[5],
        sf_p, nullptr, nullptr, Ns);

    // --- receiver self connection (independent) ---
    fctp_mma<false><<<(Nr + 127) / 128, 256, FCTP_SMEM>>>(receiver_input, receiver_attr,
        (const __nv_bfloat16*)wp[6], (const __nv_bfloat16*)wp[7],
        sc_p, nullptr, nullptr, Nr);

    // --- fused edge MLP + scatter ---
    cudaMemsetAsync(rf_p, 0, (size_t)Nr * 128 * sizeof(float));
    edge_mlp_mma<<<(E + 127) / 128, 256, EDGE_SMEM>>>(
        edge_scalars,
        (const __nv_bfloat16*)wp[0], (const __nv_bfloat16*)wp[1],
        (const __nv_bfloat16*)wp[2], (const __nv_bfloat16*)wp[3],
        sf_p, edge_src, edge_dst, edge_attr, rf_p, E);

    // --- angle + final fctp with gating epilogue ---
    angle_kernel<<<((long long)Nr * 32 + 255) / 256, 256>>>(rf_p, receiver_attr, W_lin3, ang_p, Nr);
    fctp_mma<true><<<(Nr + 127) / 128, 256, FCTP_SMEM>>>(rf_p, receiver_attr,
        (const __nv_bfloat16*)wp[8], (const __nv_bfloat16*)wp[9],
        (float*)d_out, sc_p, ang_p, Nr);
}

// round 5
// speedup vs baseline: 2.5590x; 1.0250x over previous
#include <cuda_runtime.h>
#include <cuda_bf16.h>
#include <math.h>
#include <stdint.h>

// ---------------------------------------------------------------------------
// Shapes: Ns=Nr=100000, E=600000, D=128, A=8, S=64, H=128
// ---------------------------------------------------------------------------
#define MAX_E 600000
#define MAX_N 100000

// Scratch (__device__ globals; allocation-free rule)
__device__ float g_sf [(size_t)MAX_N * 128];   // sender features
__device__ float g_sc [(size_t)MAX_N * 128];   // receiver self connection
__device__ float g_rf [(size_t)MAX_N * 128];   // scattered receiver features
__device__ float g_ang[(size_t)MAX_N];         // receiver angle
// Prepped weights, bf16; 256KB slots.
// slots 0/1: fc1 hi/lo  n-major [n][64]
// slots 2/3: fc2 hi/lo  n-major [n][128]
// slots 4/5: lin1 hi/lo v-major [v][w][u]  (8 x 128 x 128)
// slots 6/7: sc   hi/lo v-major
// slots 8/9: lin2 hi/lo v-major
__device__ __align__(1024) uint8_t g_wp[10][262144];

// ---------------------------------------------------------------------------
// mma.sync / ldmatrix / cp.async helpers (sm_80+, no arch-a gating)
// ---------------------------------------------------------------------------
__device__ __forceinline__ uint32_t smem_u32(const void* p) {
    uint32_t a;
    asm("{ .reg .u64 t; cvta.to.shared.u64 t, %1; cvt.u32.u64 %0, t; }" : "=r"(a) : "l"(p));
    return a;
}

__device__ __forceinline__ void mma16816(float* d, const uint32_t* a, const uint32_t* b) {
    asm volatile(
        "mma.sync.aligned.m16n8k16.row.col.f32.bf16.bf16.f32 "
        "{%0,%1,%2,%3}, {%4,%5,%6,%7}, {%8,%9}, {%0,%1,%2,%3};"
        : "+f"(d[0]), "+f"(d[1]), "+f"(d[2]), "+f"(d[3])
        : "r"(a[0]), "r"(a[1]), "r"(a[2]), "r"(a[3]), "r"(b[0]), "r"(b[1]));
}

__device__ __forceinline__ void ldsm4(uint32_t* r, uint32_t addr) {
    asm volatile("ldmatrix.sync.aligned.m8n8.x4.shared.b16 {%0,%1,%2,%3}, [%4];"
                 : "=r"(r[0]), "=r"(r[1]), "=r"(r[2]), "=r"(r[3]) : "r"(addr));
}

__device__ __forceinline__ void cp16(uint32_t s, const void* g) {
    asm volatile("cp.async.cg.shared.global [%0], [%1], 16;"
                 :: "r"(s), "l"(g) : "memory");
}
#define CP_COMMIT() asm volatile("cp.async.commit_group;" ::: "memory")
#define CP_WAIT0()  asm volatile("cp.async.wait_group 0;" ::: "memory")

// pack two fp32 -> bf16x2 (hi), and residual (lo)
__device__ __forceinline__ uint32_t pack_hi(float a, float b) {
    __nv_bfloat162 h = __float22bfloat162_rn(make_float2(a, b));
    return *(uint32_t*)&h;
}
__device__ __forceinline__ uint32_t pack_lo(float a, float b, uint32_t hp) {
    __nv_bfloat162 h = *(__nv_bfloat162*)&hp;
    float2 hf = __bfloat1622float2(h);
    __nv_bfloat162 l = __float22bfloat162_rn(make_float2(a - hf.x, b - hf.y));
    return *(uint32_t*)&l;
}

__device__ __forceinline__ float silu_n(float x) {
    return 1.679177f * x / (1.f + expf(-x));
}

// ---------------------------------------------------------------------------
// Merged weight prep (ONE launch):
//  fc1  -> n-major [n][64]   slots 0/1   (4096 pair jobs)
//  fc2  -> n-major [n][128]  slots 2/3   (8192 pair jobs)
//  lin1/sc/lin2 -> v-major [v][w][u] slots 4..9 (65536 pair jobs each)
// ---------------------------------------------------------------------------
__global__ void prep_all(const float* __restrict__ Wfc1, const float* __restrict__ Wfc2,
                         const float* __restrict__ Wl1,  const float* __restrict__ Wsc,
                         const float* __restrict__ Wl2,  uint8_t* __restrict__ wp)
{
    int idx = blockIdx.x * blockDim.x + threadIdx.x;
    if (idx < 4096) {                    // fc1
        int n = idx >> 5, kp = (idx & 31) << 1;
        float a = Wfc1[(size_t)kp * 128 + n];
        float b = Wfc1[(size_t)(kp + 1) * 128 + n];
        uint32_t h = pack_hi(a, b), l = pack_lo(a, b, h);
        ((uint32_t*)(wp))[n * 32 + (kp >> 1)] = h;
        ((uint32_t*)(wp + 262144))[n * 32 + (kp >> 1)] = l;
    } else if (idx < 12288) {            // fc2
        int i = idx - 4096;
        int n = i >> 6, kp = (i & 63) << 1;
        float a = Wfc2[(size_t)kp * 128 + n];
        float b = Wfc2[(size_t)(kp + 1) * 128 + n];
        uint32_t h = pack_hi(a, b), l = pack_lo(a, b, h);
        ((uint32_t*)(wp + 2 * 262144))[n * 64 + (kp >> 1)] = h;
        ((uint32_t*)(wp + 3 * 262144))[n * 64 + (kp >> 1)] = l;
    } else if (idx < 208896) {           // lin weights, v-major
        int i = idx - 12288;
        int w = i >> 16;                 // 0=lin1 1=sc 2=lin2
        int r = i & 65535;
        int v = r >> 13, n = (r >> 6) & 127, up = r & 63, u = up << 1;
        const float* W = (w == 0) ? Wl1 : (w == 1) ? Wsc : Wl2;
        float a = W[(size_t)(u * 8 + v) * 128 + n];
        float b = W[(size_t)((u + 1) * 8 + v) * 128 + n];
        uint32_t h = pack_hi(a, b), l = pack_lo(a, b, h);
        ((uint32_t*)(wp + (size_t)(4 + 2 * w) * 262144))[v * 8192 + n * 64 + up] = h;
        ((uint32_t*)(wp + (size_t)(5 + 2 * w) * 262144))[v * 8192 + n * 64 + up] = l;
    }
}

// ---------------------------------------------------------------------------
// fctp (v-loop): out[m,w] = scale * sum_v Y[m,v] * (X @ W_v)[m,w]
// Tile: 128 nodes x 128 cols, 8 warps, warp tile 32m x 64n.
// X split hi/lo ONCE into smem; per-v B double-buffered via cp.async;
// per-v GEMM (K=128, 3-pass bf16 split) into tmp regs, then fp32 Y-contraction.
// ---------------------------------------------------------------------------
static const int FCTP_SMEM = 212992;  // ys 4K + xh/xl 2x34816 + bh/bl 2x2x34816

template<bool COMBINE>
__global__ __launch_bounds__(256, 1)
void fctp_v(const float* __restrict__ X, const float* __restrict__ Y,
            const uint8_t* __restrict__ Bp,   // hi slot base; lo at +262144
            float* __restrict__ C, const float* __restrict__ SC,
            const float* __restrict__ ANG, int N)
{
    extern __shared__ uint8_t smraw[];
    float* ys = (float*)smraw;                                  // [128][8]
    __nv_bfloat16* xh = (__nv_bfloat16*)(smraw + 4096);         // [128][136]
    __nv_bfloat16* xl = xh + 17408;
    __nv_bfloat16* bh = xl + 17408;                             // [2][128][136]
    __nv_bfloat16* bl = bh + 34816;

    const int tid = threadIdx.x, wid = tid >> 5, lane = tid & 31;
    const int q = lane >> 2, t4 = lane & 3, grp = lane >> 3, rw = lane & 7;
    const int mw = (wid & 3) * 32, nw = (wid >> 2) * 64;
    const int r0 = blockIdx.x * 128;
    const uint32_t xh_a = smem_u32(xh), xl_a = smem_u32(xl);
    const uint32_t bh_a = smem_u32(bh), bl_a = smem_u32(bl);

    auto stageB = [&](int v, int b) {
        const uint8_t* sh = Bp + (size_t)v * 32768;
        const uint8_t* sl = Bp + 262144 + (size_t)v * 32768;
#pragma unroll
        for (int t = 0; t < 8; ++t) {
            int idx = tid + t * 256;
            int n = idx >> 4, seg = idx & 15;
            uint32_t d = (uint32_t)(b * 34816 + n * 272 + seg * 16);
            cp16(bh_a + d, sh + n * 256 + seg * 16);
            cp16(bl_a + d, sl + n * 256 + seg * 16);
        }
    };

    stageB(0, 0); CP_COMMIT();

    // ys
    for (int i = tid; i < 1024; i += 256) {
        int n = i >> 3, v = i & 7, r = r0 + n;
        ys[i] = (r < N) ? Y[(size_t)r * 8 + v] : 0.f;
    }

    // X split hi/lo into smem (once per tile)
    {
        int m = tid >> 1, half = tid & 1, r = r0 + m;
        const float* xr = X + (size_t)r * 128 + half * 64;
#pragma unroll
        for (int g = 0; g < 8; ++g) {
            float4 f0 = make_float4(0.f, 0.f, 0.f, 0.f), f1 = f0;
            if (r < N) {
                f0 = *(const float4*)(xr + g * 8);
                f1 = *(const float4*)(xr + g * 8 + 4);
            }
            uint32_t h[4], l[4];
            h[0] = pack_hi(f0.x, f0.y); l[0] = pack_lo(f0.x, f0.y, h[0]);
            h[1] = pack_hi(f0.z, f0.w); l[1] = pack_lo(f0.z, f0.w, h[1]);
            h[2] = pack_hi(f1.x, f1.y); l[2] = pack_lo(f1.x, f1.y, h[2]);
            h[3] = pack_hi(f1.z, f1.w); l[3] = pack_lo(f1.z, f1.w, h[3]);
            int eo = m * 136 + half * 64 + g * 8;
            *(uint4*)(xh + eo) = make_uint4(h[0], h[1], h[2], h[3]);
            *(uint4*)(xl + eo) = make_uint4(l[0], l[1], l[2], l[3]);
        }
    }

    float fin[2][8][4];
#pragma unroll
    for (int mg = 0; mg < 2; ++mg)
#pragma unroll
        for (int j = 0; j < 8; ++j)
#pragma unroll
            for (int i = 0; i < 4; ++i) fin[mg][j][i] = 0.f;

    for (int v = 0; v < 8; ++v) {
        CP_WAIT0();
        __syncthreads();
        if (v < 7) { stageB(v + 1, (v + 1) & 1); CP_COMMIT(); }

        const int b = v & 1;
        float tmp[2][8][4];
#pragma unroll
        for (int mg = 0; mg < 2; ++mg)
#pragma unroll
            for (int j = 0; j < 8; ++j)
#pragma unroll
                for (int i = 0; i < 4; ++i) tmp[mg][j][i] = 0.f;

#pragma unroll
        for (int kc = 0; kc < 8; ++kc) {
            uint32_t ah[2][4], al[2][4];
#pragma unroll
            for (int mg = 0; mg < 2; ++mg) {
                uint32_t ao = (uint32_t)((mw + 16 * mg + rw + (grp & 1) * 8) * 272
                                         + (kc * 16 + (grp >> 1) * 8) * 2);
                ldsm4(ah[mg], xh_a + ao);
                ldsm4(al[mg], xl_a + ao);
            }
#pragma unroll
            for (int jj = 0; jj < 4; ++jj) {
                int nrow = nw + 8 * (2 * jj + (grp >> 1)) + rw;
                int kcol = kc * 16 + (grp & 1) * 8;
                uint32_t off = (uint32_t)(b * 34816 + nrow * 272 + kcol * 2);
                uint32_t bhf[4], blf[4];
                ldsm4(bhf, bh_a + off);
                ldsm4(blf, bl_a + off);
#pragma unroll
                for (int mg = 0; mg < 2; ++mg) {
                    mma16816(tmp[mg][2 * jj],     ah[mg], bhf);
                    mma16816(tmp[mg][2 * jj + 1], ah[mg], bhf + 2);
                    mma16816(tmp[mg][2 * jj],     al[mg], bhf);
                    mma16816(tmp[mg][2 * jj + 1], al[mg], bhf + 2);
                    mma16816(tmp[mg][2 * jj],     ah[mg], blf);
                    mma16816(tmp[mg][2 * jj + 1], ah[mg], blf + 2);
                }
            }
        }

        // fp32 Y-contraction (no extra rounding)
#pragma unroll
        for (int mg = 0; mg < 2; ++mg) {
            float yva = ys[(mw + 16 * mg + q) * 8 + v];
            float yvb = ys[(mw + 16 * mg + q + 8) * 8 + v];
#pragma unroll
            for (int j = 0; j < 8; ++j) {
                fin[mg][j][0] += yva * tmp[mg][j][0];
                fin[mg][j][1] += yva * tmp[mg][j][1];
                fin[mg][j][2] += yvb * tmp[mg][j][2];
                fin[mg][j][3] += yvb * tmp[mg][j][3];
            }
        }
    }

    // epilogue
    const float sk = 0.03125f;   // 1/sqrt(128*8)
#pragma unroll
    for (int mg = 0; mg < 2; ++mg) {
#pragma unroll
        for (int h = 0; h < 2; ++h) {
            int m = r0 + mw + 16 * mg + 8 * h + q;
            if (m >= N) continue;
            float ca = 1.f, sa = 0.f;
            if (COMBINE) { float a = ANG[m]; ca = cosf(a); sa = sinf(a); }
#pragma unroll
            for (int j = 0; j < 8; ++j) {
                int col = nw + 8 * j + 2 * t4;
                float2 val = make_float2(fin[mg][j][2 * h] * sk, fin[mg][j][2 * h + 1] * sk);
                if (COMBINE) {
                    const float* sp = SC + (size_t)m * 128 + col;
                    val.x = ca * sp[0] + sa * val.x;
                    val.y = ca * sp[1] + sa * val.y;
                }
                *(float2*)(C + (size_t)m * 128 + col) = val;
            }
        }
    }
}

// ---------------------------------------------------------------------------
// Fused edge MLP + scatter (unchanged from R4):
//   wt = (SILU_NORM*silu(es@W1/8)) @ W2 / sqrt(128) ; rf[dst] += wt*sf[src]*ea/sqrt(32)
// ---------------------------------------------------------------------------
static const int EDGE_SMEM = (9216 * 4 + 17408 * 2) * 2;   // 143360 B

__global__ __launch_bounds__(256)
void edge_mlp_mma(const float* __restrict__ ES,
                  const __nv_bfloat16* __restrict__ B1h, const __nv_bfloat16* __restrict__ B1l,
                  const __nv_bfloat16* __restrict__ B2h, const __nv_bfloat16* __restrict__ B2l,
                  const float* __restrict__ SF, const int* __restrict__ SRC,
                  const int* __restrict__ DST, const float* __restrict__ EA,
                  float* __restrict__ RF, int E)
{
    extern __shared__ __align__(16) __nv_bfloat16 sm[];
    __nv_bfloat16* ash = sm;              // [128][72]
    __nv_bfloat16* asl = sm + 9216;
    __nv_bfloat16* b1h = sm + 18432;      // [128][72]
    __nv_bfloat16* b1l = sm + 27648;
    __nv_bfloat16* b2h = sm + 36864;      // [128][136]
    __nv_bfloat16* b2l = sm + 54272;

    const int tid = threadIdx.x, wid = tid >> 5, lane = tid & 31;
    const int e0 = blockIdx.x * 128;

    for (int i = tid; i < 4096; i += 256) {
        int m = i >> 5, kp = (i & 31) * 2;
        int e = e0 + m;
        float v0 = 0.f, v1 = 0.f;
        if (e < E) {
            v0 = ES[(size_t)e * 64 + kp];
            v1 = ES[(size_t)e * 64 + kp + 1];
        }
        uint32_t hp = pack_hi(v0, v1);
        uint32_t lp = pack_lo(v0, v1, hp);
        *(uint32_t*)(ash + m * 72 + kp) = hp;
        *(uint32_t*)(asl + m * 72 + kp) = lp;
    }
    for (int i = tid; i < 1024; i += 256) {
        int n = i >> 3, seg = i & 7;
        *(uint4*)(b1h + n * 72 + seg * 8) = *(const uint4*)(B1h + (size_t)n * 64 + seg * 8);
        *(uint4*)(b1l + n * 72 + seg * 8) = *(const uint4*)(B1l + (size_t)n * 64 + seg * 8);
    }
    for (int i = tid; i < 2048; i += 256) {
        int n = i >> 4, seg = i & 15;
        *(uint4*)(b2h + n * 136 + seg * 8) = *(const uint4*)(B2h + (size_t)n * 128 + seg * 8);
        *(uint4*)(b2l + n * 136 + seg * 8) = *(const uint4*)(B2l + (size_t)n * 128 + seg * 8);
    }
    __syncthreads();

    const int q = lane >> 2, t4 = lane & 3;
    const int grp = lane >> 3, rw = lane & 7;
    const uint32_t sa_h = smem_u32(ash), sa_l = smem_u32(asl);
    const uint32_t s1h = smem_u32(b1h), s1l = smem_u32(b1l);
    const uint32_t s2h = smem_u32(b2h), s2l = smem_u32(b2l);

    float acc1[16][4];
#pragma unroll
    for (int j = 0; j < 16; ++j)
#pragma unroll
        for (int i = 0; i < 4; ++i) acc1[j][i] = 0.f;

#pragma unroll
    for (int s = 0; s < 4; ++s) {
        int mrow = wid * 16 + rw + (grp & 1) * 8;
        int kcol = s * 16 + (grp >> 1) * 8;
        uint32_t aoffs = (uint32_t)(mrow * 72 + kcol) * 2;
        uint32_t ah[4], al[4];
        ldsm4(ah, sa_h + aoffs);
        ldsm4(al, sa_l + aoffs);
#pragma unroll
        for (int jj = 0; jj < 8; ++jj) {
            int nrow = 8 * (2 * jj + (grp >> 1)) + rw;
            int kc = s * 16 + (grp & 1) * 8;
            uint32_t off = (uint32_t)(nrow * 72 + kc) * 2;
            uint32_t bh[4], bl[4];
            ldsm4(bh, s1h + off);
            ldsm4(bl, s1l + off);
            mma16816(acc1[2 * jj],     ah, bh);
            mma16816(acc1[2 * jj + 1], ah, bh + 2);
            mma16816(acc1[2 * jj],     al, bh);
            mma16816(acc1[2 * jj + 1], al, bh + 2);
            mma16816(acc1[2 * jj],     ah, bl);
            mma16816(acc1[2 * jj + 1], ah, bl + 2);
        }
    }

#pragma unroll
    for (int j = 0; j < 16; ++j)
#pragma unroll
        for (int i = 0; i < 4; ++i) acc1[j][i] = silu_n(acc1[j][i] * 0.125f);

    float acc2[16][4];
#pragma unroll
    for (int j = 0; j < 16; ++j)
#pragma unroll
        for (int i = 0; i < 4; ++i) acc2[j][i] = 0.f;

#pragma unroll
    for (int s = 0; s < 8; ++s) {
        uint32_t ah[4], al[4];
        ah[0] = pack_hi(acc1[2 * s][0],     acc1[2 * s][1]);
        al[0] = pack_lo(acc1[2 * s][0],     acc1[2 * s][1],     ah[0]);
        ah[1] = pack_hi(acc1[2 * s][2],     acc1[2 * s][3]);
        al[1] = pack_lo(acc1[2 * s][2],     acc1[2 * s][3],     ah[1]);
        ah[2] = pack_hi(acc1[2 * s + 1][0], acc1[2 * s + 1][1]);
        al[2] = pack_lo(acc1[2 * s + 1][0], acc1[2 * s + 1][1], ah[2]);
        ah[3] = pack_hi(acc1[2 * s + 1][2], acc1[2 * s + 1][3]);
        al[3] = pack_lo(acc1[2 * s + 1][2], acc1[2 * s + 1][3], ah[3]);
#pragma unroll
        for (int jj = 0; jj < 8; ++jj) {
            int nrow = 8 * (2 * jj + (grp >> 1)) + rw;
            int kc = s * 16 + (grp & 1) * 8;
            uint32_t off = (uint32_t)(nrow * 136 + kc) * 2;
            uint32_t bh[4], bl[4];
            ldsm4(bh, s2h + off);
            ldsm4(bl, s2l + off);
            mma16816(acc2[2 * jj],     ah, bh);
            mma16816(acc2[2 * jj + 1], ah, bh + 2);
            mma16816(acc2[2 * jj],     al, bh);
            mma16816(acc2[2 * jj + 1], al, bh + 2);
            mma16816(acc2[2 * jj],     ah, bl);
            mma16816(acc2[2 * jj + 1], ah, bl + 2);
        }
    }

    const float sk = 0.08838834764831845f;   // 1/sqrt(128)
#pragma unroll
    for (int h = 0; h < 2; ++h) {
        int er = e0 + wid * 16 + 8 * h + q;
        if (er >= E) continue;
        int sidx = SRC[er], didx = DST[er];
        float ea = EA[er] * 0.17677669529663687f * sk;
        const float* sfr = SF + (size_t)sidx * 128;
        float* rfr = RF + (size_t)didx * 128;
#pragma unroll
        for (int j = 0; j < 16; ++j) {
            int col = 8 * j + 2 * t4;
            float2 s2 = *(const float2*)(sfr + col);
            atomicAdd(rfr + col,     acc2[j][2 * h]     * ea * s2.x);
            atomicAdd(rfr + col + 1, acc2[j][2 * h + 1] * ea * s2.y);
        }
    }
}

// ---------------------------------------------------------------------------
// Angle: ang[n] = 0.1/32 * sum_{u,v} rf[n,u] rattr[n,v] W3[u*8+v]; warp/node
// ---------------------------------------------------------------------------
__global__ void angle_kernel(const float* __restrict__ RF, const float* __restrict__ RA,
                             const float* __restrict__ W3, float* __restrict__ ANG, int N)
{
    int gw   = (blockIdx.x * blockDim.x + threadIdx.x) >> 5;
    int lane = threadIdx.x & 31;
    if (gw >= N) return;
    float ya[8];
#pragma unroll
    for (int v = 0; v < 8; ++v) ya[v] = RA[(size_t)gw * 8 + v];
    float sacc = 0.f;
#pragma unroll
    for (int uu = 0; uu < 4; ++uu) {
        int u = lane + uu * 32;
        float xv = RF[(size_t)gw * 128 + u];
#pragma unroll
        for (int v = 0; v < 8; ++v) sacc += xv * ya[v] * W3[u * 8 + v];
    }
#pragma unroll
    for (int off = 16; off; off >>= 1) sacc += __shfl_xor_sync(0xffffffffu, sacc, off);
    if (lane == 0) ANG[gw] = 0.003125f * sacc;   // 0.1 / 32
}

// ---------------------------------------------------------------------------
extern "C" void kernel_launch(void* const* d_in, const int* in_sizes, int n_in,
                              void* d_out, int out_size)
{
    const float* sender_input   = (const float*)d_in[0];
    const float* sender_attr    = (const float*)d_in[1];
    const float* receiver_input = (const float*)d_in[2];
    const float* receiver_attr  = (const float*)d_in[3];
    const int*   edge_src       = (const int*)  d_in[4];
    const int*   edge_dst       = (const int*)  d_in[5];
    const float* edge_attr      = (const float*)d_in[6];
    const float* edge_scalars   = (const float*)d_in[7];
    const float* W_sc           = (const float*)d_in[8];
    const float* W_lin1         = (const float*)d_in[9];
    const float* W_fc1          = (const float*)d_in[10];
    const float* W_fc2          = (const float*)d_in[11];
    const float* W_lin2         = (const float*)d_in[12];
    const float* W_lin3         = (const float*)d_in[13];

    const int Ns = in_sizes[0] / 128;
    const int Nr = in_sizes[2] / 128;
    const int E  = in_sizes[4];

    float *sf_p, *sc_p, *rf_p, *ang_p;
    uint8_t* wp;
    cudaGetSymbolAddress((void**)&sf_p,  g_sf);
    cudaGetSymbolAddress((void**)&sc_p,  g_sc);
    cudaGetSymbolAddress((void**)&rf_p,  g_rf);
    cudaGetSymbolAddress((void**)&ang_p, g_ang);
    cudaGetSymbolAddress((void**)&wp,    g_wp);

    cudaFuncSetAttribute(edge_mlp_mma,  cudaFuncAttributeMaxDynamicSharedMemorySize, EDGE_SMEM);
    cudaFuncSetAttribute(fctp_v<false>, cudaFuncAttributeMaxDynamicSharedMemorySize, FCTP_SMEM);
    cudaFuncSetAttribute(fctp_v<true>,  cudaFuncAttributeMaxDynamicSharedMemorySize, FCTP_SMEM);

    // --- single merged weight prep (208896 pair-jobs) ---
    prep_all<<<816, 256>>>(W_fc1, W_fc2, W_lin1, W_sc, W_lin2, wp);

    cudaMemsetAsync(rf_p, 0, (size_t)Nr * 128 * sizeof(float));

    // --- sender features ---
    fctp_v<false><<<(Ns + 127) / 128, 256, FCTP_SMEM>>>(sender_input, sender_attr,
        wp + 4 * 262144, sf_p, nullptr, nullptr, Ns);

    // --- receiver self connection ---
    fctp_v<false><<<(Nr + 127) / 128, 256, FCTP_SMEM>>>(receiver_input, receiver_attr,
        wp + 6 * 262144, sc_p, nullptr, nullptr, Nr);

    // --- fused edge MLP + scatter ---
    edge_mlp_mma<<<(E + 127) / 128, 256, EDGE_SMEM>>>(
        edge_scalars,
        (const __nv_bfloat16*)wp, (const __nv_bfloat16*)(wp + 262144),
        (const __nv_bfloat16*)(wp + 2 * 262144), (const __nv_bfloat16*)(wp + 3 * 262144),
        sf_p, edge_src, edge_dst, edge_attr, rf_p, E);

    // --- angle + final fctp with gating epilogue ---
    angle_kernel<<<((long long)Nr * 32 + 255) / 256, 256>>>(rf_p, receiver_attr, W_lin3, ang_p, Nr);
    fctp_v<true><<<(Nr + 127) / 128, 256, FCTP_SMEM>>>(rf_p, receiver_attr,
        wp + 8 * 262144, (float*)d_out, sc_p, ang_p, Nr);
}